// round 7
// baseline (speedup 1.0000x reference)
#include <cuda_runtime.h>
#include <math.h>

#define MAXN 50000
#define MAXE 800000

typedef unsigned long long u64;

// ---------------- scratch (static device globals; no allocs allowed) ----------------
__device__ int   g_cnt[MAXN];            // zeroed at static init; scan re-zeroes after read
__device__ int   g_off[MAXN + 1];
__device__ int   g_cursor[MAXN];
__device__ volatile u64 g_state[64];     // lookback states; zeroed by k_count block 0
__device__ float g_dis[MAXN];
__device__ int2  g_csr[MAXE];            // {src row, float bits of dis[src]}
__device__ float g_xw1[(size_t)MAXN * 64];  // x@W1 (raw)
__device__ float g_h  [(size_t)MAXN * 64];  // relu(layer1)
__device__ float g_xw2[(size_t)MAXN * 64];  // h@W2 (raw)
__device__ float g_z  [(size_t)MAXN * 64];  // layer2 out

// ---------------- streams/events (host-side, created once) ----------------
static cudaStream_t g_s2;
static cudaEvent_t  g_evF, g_evJ;
struct _AthInit {
    _AthInit() {
        cudaStreamCreateWithFlags(&g_s2, cudaStreamNonBlocking);
        cudaEventCreateWithFlags(&g_evF, cudaEventDisableTiming);
        cudaEventCreateWithFlags(&g_evJ, cudaEventDisableTiming);
    }
};
static _AthInit _ath_init;

// ---------------- packed fp32x2 helpers ----------------
__device__ __forceinline__ u64 pk2(float a, float b) {
    u64 r; asm("mov.b64 %0, {%1, %2};" : "=l"(r) : "f"(a), "f"(b)); return r;
}
__device__ __forceinline__ void fma2(u64& d, u64 a, u64 b) {
    asm("fma.rn.f32x2 %0, %1, %2, %0;" : "+l"(d) : "l"(a), "l"(b));
}
__device__ __forceinline__ float2 up2(u64 v) {
    float2 r; asm("mov.b64 {%0, %1}, %2;" : "=f"(r.x), "=f"(r.y) : "l"(v)); return r;
}

// ---------------- CSR build ----------------
__global__ void k_count(const int* __restrict__ ei, int nE) {
    if (blockIdx.x == 0 && threadIdx.x < 64) g_state[threadIdx.x] = 0;
    int e = blockIdx.x * blockDim.x + threadIdx.x;
    if (e < nE) atomicAdd(&g_cnt[ei[nE + e]], 1);  // col = target
}

// fused scan: exclusive offsets + cursor init + dis, single kernel.
__global__ void k_scan_fused(int n, int nb) {
    __shared__ int s[1024];
    __shared__ int s_excl;
    __shared__ int r64[2];
    int b = blockIdx.x, t = threadIdx.x;
    int i = b * 1024 + t;
    int v = (i < n) ? g_cnt[i] : 0;
    if (i < n) g_cnt[i] = 0;              // restore invariant for next replay
    s[t] = v;
    __syncthreads();
#pragma unroll
    for (int dd = 1; dd < 1024; dd <<= 1) {
        int x = (t >= dd) ? s[t - dd] : 0;
        __syncthreads();
        s[t] += x;
        __syncthreads();
    }
    int incl = s[t];
    if (t == 1023)
        g_state[b] = (1ull << 32) | (unsigned)incl;   // publish block aggregate
    if (t < 64) {
        int val = 0;
        if (t < b) {
            u64 st;
            do { st = g_state[t]; } while (!(st >> 32));
            val = (int)(unsigned)st;
        }
#pragma unroll
        for (int o = 16; o; o >>= 1) val += __shfl_down_sync(0xffffffffu, val, o);
        if ((t & 31) == 0) r64[t >> 5] = val;
    }
    __syncthreads();
    if (t == 0) s_excl = r64[0] + r64[1];
    __syncthreads();
    int ex = s_excl;
    if (i < n) {
        int o = ex + incl - v;
        g_off[i] = o;
        g_cursor[i] = o;
        g_dis[i] = rsqrtf((float)(v + 1));   // deg = in-degree + self-loop
    }
    if (b == nb - 1 && t == 1023) g_off[n] = ex + incl;
}

__global__ void k_scatter(const int* __restrict__ ei, int nE) {
    int e = blockIdx.x * blockDim.x + threadIdx.x;
    if (e < nE) {
        int row = ei[e];
        int col = ei[nE + e];
        int p = atomicAdd(&g_cursor[col], 1);
        g_csr[p] = make_int2(row, __float_as_int(g_dis[row]));
    }
}

// ---------------- GEMM (raw): out[r][c] = A[r][:] @ W[:][c] ----------------
// Block tile 256 rows x 64 cols, 256 threads, thread tile 8 rows x 8 cols.
// k-chunk 32, xs pitch 33. Per thread per k: 32B w + 32B x for 64 MACs (1 B/MAC).
template <int K>
__global__ void __launch_bounds__(256) k_gemm(const float* __restrict__ A,
                                              const float* __restrict__ W,
                                              float* __restrict__ out, int n) {
    __shared__ float xs[256][33];   // rows x k-chunk (pitch 33)
    __shared__ float ws[32][64];    // k x cols
    int t = threadIdx.x;
    int tx = t & 7;        // col group (x8)
    int ty = t >> 3;       // row group (x8), 0..31
    int row0 = blockIdx.x * 256;

    u64 acc[8][4] = {};    // 8 rows x 4 packed col-pairs (8 cols)

    for (int kc = 0; kc < K; kc += 32) {
        // x tile: 256 rows x 32 k = 2048 float4 slots, 8 per thread
#pragma unroll
        for (int it = 0; it < 8; it++) {
            int v = it * 256 + t;
            int r = v >> 3;              // 0..255
            int q = v & 7;               // 0..7 float4 within row
            int gr = min(row0 + r, n - 1);
            float4 xv = *(const float4*)(A + (size_t)gr * K + kc + q * 4);
            xs[r][q * 4 + 0] = xv.x;
            xs[r][q * 4 + 1] = xv.y;
            xs[r][q * 4 + 2] = xv.z;
            xs[r][q * 4 + 3] = xv.w;
        }
        // w tile: 32 k x 64 cols = 512 float4 slots, 2 per thread
#pragma unroll
        for (int it = 0; it < 2; it++) {
            int v = it * 256 + t;
            int r = v >> 4;              // 0..31
            int q = v & 15;              // 0..15
            *(float4*)&ws[r][q * 4] = *(const float4*)(W + (size_t)(kc + r) * 64 + q * 4);
        }
        __syncthreads();

#pragma unroll 4
        for (int k = 0; k < 32; k++) {
            u64 w[4];
            *(ulonglong2*)&w[0] = *(const ulonglong2*)&ws[k][tx * 8];
            *(ulonglong2*)&w[2] = *(const ulonglong2*)&ws[k][tx * 8 + 4];
#pragma unroll
            for (int i = 0; i < 8; i++) {
                float xf = xs[ty * 8 + i][k];
                u64 xd = pk2(xf, xf);
                fma2(acc[i][0], xd, w[0]);
                fma2(acc[i][1], xd, w[1]);
                fma2(acc[i][2], xd, w[2]);
                fma2(acc[i][3], xd, w[3]);
            }
        }
        __syncthreads();
    }

#pragma unroll
    for (int i = 0; i < 8; i++) {
        int r = row0 + ty * 8 + i;
        if (r < n) {
            float2 p0 = up2(acc[i][0]);
            float2 p1 = up2(acc[i][1]);
            float2 p2 = up2(acc[i][2]);
            float2 p3 = up2(acc[i][3]);
            float4 o0; o0.x = p0.x; o0.y = p0.y; o0.z = p1.x; o0.w = p1.y;
            float4 o1; o1.x = p2.x; o1.y = p2.y; o1.z = p3.x; o1.w = p3.y;
            *(float4*)(out + (size_t)r * 64 + tx * 8)     = o0;
            *(float4*)(out + (size_t)r * 64 + tx * 8 + 4) = o1;
        }
    }
}

// ---------------- Aggregation (warp per node, float2 per lane) ----------------
// out[i] = act( dis[i]*( sum_in xw[row]*dis[row] + xw[i]*dis[i] ) + b )
__global__ void k_aggregate(const float* __restrict__ in, float* __restrict__ out,
                            const float* __restrict__ bias, int n, int relu) {
    int node = blockIdx.x * 8 + (threadIdx.x >> 5);
    int lane = threadIdx.x & 31;
    if (node >= n) return;
    const float2* inp = (const float2*)in;
    float d = g_dis[node];
    float2 acc = inp[(size_t)node * 32 + lane];
    acc.x *= d; acc.y *= d;                     // self-loop: xw[i]*dis[i]
    int s = g_off[node], e = g_off[node + 1];
    for (int base = s; base < e; base += 32) {
        int idx = base + lane;
        int2 pr = (idx < e) ? g_csr[idx] : make_int2(0, 0);
        int cnt = min(32, e - base);
        for (int j = 0; j < cnt; j++) {
            int row  = __shfl_sync(0xffffffffu, pr.x, j);
            float dw = __int_as_float(__shfl_sync(0xffffffffu, pr.y, j));
            float2 v = inp[(size_t)row * 32 + lane];
            acc.x = fmaf(v.x, dw, acc.x);
            acc.y = fmaf(v.y, dw, acc.y);
        }
    }
    float2 bv = ((const float2*)bias)[lane];
    float ox = fmaf(d, acc.x, bv.x);
    float oy = fmaf(d, acc.y, bv.y);
    if (relu) { ox = fmaxf(ox, 0.f); oy = fmaxf(oy, 0.f); }
    float2 o; o.x = ox; o.y = oy;
    ((float2*)out)[(size_t)node * 32 + lane] = o;
}

// ---------------- Decode: out[e] = dot(z[src], z[dst]) ----------------
__global__ void k_decode(const int* __restrict__ eli, const float* __restrict__ z,
                         float* __restrict__ out, int nL) {
    int w = blockIdx.x * 8 + (threadIdx.x >> 5);
    int lane = threadIdx.x & 31;
    if (w >= nL) return;
    int s = eli[w];
    int d = eli[nL + w];
    const float2* z2 = (const float2*)z;
    float2 a = z2[(size_t)s * 32 + lane];
    float2 b = z2[(size_t)d * 32 + lane];
    float p = a.x * b.x + a.y * b.y;
#pragma unroll
    for (int o = 16; o > 0; o >>= 1) p += __shfl_down_sync(0xffffffffu, p, o);
    if (lane == 0) out[w] = p;
}

// ---------------- launch ----------------
extern "C" void kernel_launch(void* const* d_in, const int* in_sizes, int n_in,
                              void* d_out, int out_size) {
    const float* x   = (const float*)d_in[0];
    const int*   ei  = (const int*)  d_in[1];
    const int*   eli = (const int*)  d_in[2];
    const float* W1  = (const float*)d_in[3];
    const float* b1  = (const float*)d_in[4];
    const float* W2  = (const float*)d_in[5];
    const float* b2  = (const float*)d_in[6];
    float* out = (float*)d_out;

    int n  = in_sizes[0] / 256;
    int nE = in_sizes[1] / 2;
    int nL = in_sizes[2] / 2;

    void *p_xw1, *p_h, *p_xw2, *p_z;
    cudaGetSymbolAddress(&p_xw1, g_xw1);
    cudaGetSymbolAddress(&p_h,   g_h);
    cudaGetSymbolAddress(&p_xw2, g_xw2);
    cudaGetSymbolAddress(&p_z,   g_z);

    // Fork: CSR build on side stream, GEMM1 concurrently on main stream.
    cudaEventRecord(g_evF, 0);
    cudaStreamWaitEvent(g_s2, g_evF, 0);

    k_count<<<(nE + 255) / 256, 256, 0, g_s2>>>(ei, nE);
    int nb = (n + 1023) / 1024;
    k_scan_fused<<<nb, 1024, 0, g_s2>>>(n, nb);
    k_scatter<<<(nE + 255) / 256, 256, 0, g_s2>>>(ei, nE);
    cudaEventRecord(g_evJ, g_s2);

    int gb = (n + 255) / 256;
    k_gemm<256><<<gb, 256>>>(x, W1, (float*)p_xw1, n);   // concurrent with CSR

    // Join
    cudaStreamWaitEvent(0, g_evJ, 0);

    // layer 1 aggregate
    k_aggregate<<<(n + 7) / 8, 256>>>((const float*)p_xw1, (float*)p_h, b1, n, 1);
    // layer 2
    k_gemm<64><<<gb, 256>>>((const float*)p_h, W2, (float*)p_xw2, n);
    k_aggregate<<<(n + 7) / 8, 256>>>((const float*)p_xw2, (float*)p_z, b2, n, 0);
    // decode
    k_decode<<<(nL + 7) / 8, 256>>>(eli, (const float*)p_z, out, nL);
}

// round 8
// speedup vs baseline: 2.0818x; 2.0818x over previous
#include <cuda_runtime.h>
#include <cuda_bf16.h>
#include <math.h>

#define MAXN 50000
#define MAXE 800000

typedef unsigned long long u64;

// ---------------- scratch (static device globals; no allocs allowed) ----------------
__device__ int   g_cnt[MAXN];            // zeroed at static init; scan re-zeroes after read
__device__ int   g_off[MAXN + 1];
__device__ int   g_cursor[MAXN];
__device__ volatile u64 g_state[64];     // lookback states; zeroed by k_count block 0
__device__ float g_dis[MAXN];
__device__ int2  g_csr[MAXE];            // {src row, float bits of dis[src]}
__device__ float g_xw1[(size_t)MAXN * 64];  // x@W1 (raw)
__device__ float g_h  [(size_t)MAXN * 64];  // relu(layer1)
__device__ float g_xw2[(size_t)MAXN * 64];  // h@W2 (raw)
__device__ float g_z  [(size_t)MAXN * 64];  // layer2 out

// ---------------- streams/events (host-side, created once) ----------------
static cudaStream_t g_s2;
static cudaEvent_t  g_evF, g_evJ;
struct _AthInit {
    _AthInit() {
        cudaStreamCreateWithFlags(&g_s2, cudaStreamNonBlocking);
        cudaEventCreateWithFlags(&g_evF, cudaEventDisableTiming);
        cudaEventCreateWithFlags(&g_evJ, cudaEventDisableTiming);
    }
};
static _AthInit _ath_init;

// ---------------- CSR build ----------------
__global__ void k_count(const int* __restrict__ ei, int nE) {
    if (blockIdx.x == 0 && threadIdx.x < 64) g_state[threadIdx.x] = 0;
    int e = blockIdx.x * blockDim.x + threadIdx.x;
    if (e < nE) atomicAdd(&g_cnt[ei[nE + e]], 1);  // col = target
}

// fused scan: exclusive offsets + cursor init + dis, single kernel.
__global__ void k_scan_fused(int n, int nb) {
    __shared__ int s[1024];
    __shared__ int s_excl;
    __shared__ int r64[2];
    int b = blockIdx.x, t = threadIdx.x;
    int i = b * 1024 + t;
    int v = (i < n) ? g_cnt[i] : 0;
    if (i < n) g_cnt[i] = 0;              // restore invariant for next replay
    s[t] = v;
    __syncthreads();
#pragma unroll
    for (int dd = 1; dd < 1024; dd <<= 1) {
        int x = (t >= dd) ? s[t - dd] : 0;
        __syncthreads();
        s[t] += x;
        __syncthreads();
    }
    int incl = s[t];
    if (t == 1023)
        g_state[b] = (1ull << 32) | (unsigned)incl;   // publish block aggregate
    if (t < 64) {
        int val = 0;
        if (t < b) {
            u64 st;
            do { st = g_state[t]; } while (!(st >> 32));
            val = (int)(unsigned)st;
        }
#pragma unroll
        for (int o = 16; o; o >>= 1) val += __shfl_down_sync(0xffffffffu, val, o);
        if ((t & 31) == 0) r64[t >> 5] = val;
    }
    __syncthreads();
    if (t == 0) s_excl = r64[0] + r64[1];
    __syncthreads();
    int ex = s_excl;
    if (i < n) {
        int o = ex + incl - v;
        g_off[i] = o;
        g_cursor[i] = o;
        g_dis[i] = rsqrtf((float)(v + 1));   // deg = in-degree + self-loop
    }
    if (b == nb - 1 && t == 1023) g_off[n] = ex + incl;
}

__global__ void k_scatter(const int* __restrict__ ei, int nE) {
    int e = blockIdx.x * blockDim.x + threadIdx.x;
    if (e < nE) {
        int row = ei[e];
        int col = ei[nE + e];
        int p = atomicAdd(&g_cursor[col], 1);
        g_csr[p] = make_int2(row, __float_as_int(g_dis[row]));
    }
}

// ---------------- tensor-core GEMM with bf16 2-term split ----------------
// D = xh@Wh + xh@Wl + xl@Wh  (fp32 accum; dropped xl@Wl ~ 2^-18 rel)
__device__ __forceinline__ void split_pack(float a, float b, unsigned& hi, unsigned& lo) {
    __nv_bfloat16 ha = __float2bfloat16_rn(a), hb = __float2bfloat16_rn(b);
    float ra = a - __bfloat162float(ha);
    float rb = b - __bfloat162float(hb);
    __nv_bfloat16 la = __float2bfloat16_rn(ra), lb = __float2bfloat16_rn(rb);
    hi = ((unsigned)__bfloat16_as_ushort(hb) << 16) | (unsigned)__bfloat16_as_ushort(ha);
    lo = ((unsigned)__bfloat16_as_ushort(lb) << 16) | (unsigned)__bfloat16_as_ushort(la);
}

__device__ __forceinline__ void ldsm4(unsigned* r, unsigned addr) {
    asm volatile("ldmatrix.sync.aligned.m8n8.x4.shared.b16 {%0,%1,%2,%3}, [%4];"
        : "=r"(r[0]), "=r"(r[1]), "=r"(r[2]), "=r"(r[3]) : "r"(addr));
}
__device__ __forceinline__ void ldsm4t(unsigned* r, unsigned addr) {
    asm volatile("ldmatrix.sync.aligned.m8n8.x4.trans.shared.b16 {%0,%1,%2,%3}, [%4];"
        : "=r"(r[0]), "=r"(r[1]), "=r"(r[2]), "=r"(r[3]) : "r"(addr));
}
__device__ __forceinline__ void mma16816(float* c, const unsigned* a, const unsigned* b) {
    asm volatile(
        "mma.sync.aligned.m16n8k16.row.col.f32.bf16.bf16.f32 "
        "{%0,%1,%2,%3}, {%4,%5,%6,%7}, {%8,%9}, {%0,%1,%2,%3};"
        : "+f"(c[0]), "+f"(c[1]), "+f"(c[2]), "+f"(c[3])
        : "r"(a[0]), "r"(a[1]), "r"(a[2]), "r"(a[3]), "r"(b[0]), "r"(b[1]));
}

// Block tile 128(M) x 64(N), 256 threads = 8 warps (4M x 2N), warp tile 32x32.
// A [n,K] fp32 row-major, W [K,64] fp32 row-major, out [n,64] fp32.
template <int K>
__global__ void __launch_bounds__(256) k_gemm_mma(const float* __restrict__ A,
                                                  const float* __restrict__ W,
                                                  float* __restrict__ out, int n) {
    constexpr int PA = 40;   // bf16 pitch for x tiles (80B: conflict-free ldmatrix)
    constexpr int PB = 72;   // bf16 pitch for w tiles (144B: conflict-free ldmatrix)
    __shared__ __align__(16) __nv_bfloat16 xh[128 * PA], xl[128 * PA];
    __shared__ __align__(16) __nv_bfloat16 wh[32 * PB],  wl[32 * PB];
    int t = threadIdx.x;
    int lane = t & 31, wrp = t >> 5;
    int wm = wrp & 3, wn = wrp >> 2;
    int row0 = blockIdx.x * 128;

    float acc[2][4][4] = {};

    unsigned sxh = (unsigned)__cvta_generic_to_shared(xh);
    unsigned sxl = (unsigned)__cvta_generic_to_shared(xl);
    unsigned swh = (unsigned)__cvta_generic_to_shared(wh);
    unsigned swl = (unsigned)__cvta_generic_to_shared(wl);

    for (int kc = 0; kc < K; kc += 32) {
        // stage x tile: 128 rows x 32 k, convert fp32 -> (hi, lo) bf16
#pragma unroll
        for (int it = 0; it < 4; it++) {
            int v = it * 256 + t;          // 1024 chunks of 4 floats
            int r = v >> 3, ch = v & 7;
            int gr = min(row0 + r, n - 1);
            float4 xv = *(const float4*)(A + (size_t)gr * K + kc + ch * 4);
            uint2 h, l;
            split_pack(xv.x, xv.y, h.x, l.x);
            split_pack(xv.z, xv.w, h.y, l.y);
            *(uint2*)&xh[r * PA + ch * 4] = h;
            *(uint2*)&xl[r * PA + ch * 4] = l;
        }
        // stage w tile: 32 k x 64 cols
#pragma unroll
        for (int it = 0; it < 2; it++) {
            int v = it * 256 + t;          // 512 chunks of 4 floats
            int r = v >> 4, c = v & 15;
            float4 wv = *(const float4*)(W + (size_t)(kc + r) * 64 + c * 4);
            uint2 h, l;
            split_pack(wv.x, wv.y, h.x, l.x);
            split_pack(wv.z, wv.w, h.y, l.y);
            *(uint2*)&wh[r * PB + c * 4] = h;
            *(uint2*)&wl[r * PB + c * 4] = l;
        }
        __syncthreads();

#pragma unroll
        for (int ks = 0; ks < 32; ks += 16) {
            unsigned ah[2][4], al[2][4], bh[2][4], bl[2][4];
#pragma unroll
            for (int mi = 0; mi < 2; mi++) {
                int rrow = wm * 32 + mi * 16 + (lane & 15);
                unsigned off = (unsigned)(rrow * PA + ks) * 2 + (lane >> 4) * 16;
                ldsm4(ah[mi], sxh + off);
                ldsm4(al[mi], sxl + off);
            }
#pragma unroll
            for (int nb = 0; nb < 2; nb++) {
                int kk = ks + (lane & 7) + ((lane >> 3) & 1) * 8;
                int nc = wn * 32 + nb * 16 + (lane >> 4) * 8;
                unsigned off = (unsigned)(kk * PB + nc) * 2;
                ldsm4t(bh[nb], swh + off);
                ldsm4t(bl[nb], swl + off);
            }
#pragma unroll
            for (int mi = 0; mi < 2; mi++)
#pragma unroll
                for (int nb = 0; nb < 2; nb++)
#pragma unroll
                    for (int q = 0; q < 2; q++) {
                        float* c = acc[mi][nb * 2 + q];
                        mma16816(c, ah[mi], &bh[nb][q * 2]);
                        mma16816(c, ah[mi], &bl[nb][q * 2]);
                        mma16816(c, al[mi], &bh[nb][q * 2]);
                    }
        }
        __syncthreads();
    }

    // epilogue: c0,c1 -> (row, col..col+1); c2,c3 -> (row+8, ...)
#pragma unroll
    for (int mi = 0; mi < 2; mi++) {
#pragma unroll
        for (int nj = 0; nj < 4; nj++) {
            int col = wn * 32 + nj * 8 + (lane & 3) * 2;
            int r0 = row0 + wm * 32 + mi * 16 + (lane >> 2);
            if (r0 < n)
                *(float2*)(out + (size_t)r0 * 64 + col) =
                    make_float2(acc[mi][nj][0], acc[mi][nj][1]);
            int r1 = r0 + 8;
            if (r1 < n)
                *(float2*)(out + (size_t)r1 * 64 + col) =
                    make_float2(acc[mi][nj][2], acc[mi][nj][3]);
        }
    }
}

// ---------------- Aggregation (warp per node, float2 per lane) ----------------
// out[i] = act( dis[i]*( sum_in xw[row]*dis[row] + xw[i]*dis[i] ) + b )
__global__ void k_aggregate(const float* __restrict__ in, float* __restrict__ out,
                            const float* __restrict__ bias, int n, int relu) {
    int node = blockIdx.x * 8 + (threadIdx.x >> 5);
    int lane = threadIdx.x & 31;
    if (node >= n) return;
    const float2* inp = (const float2*)in;
    float d = g_dis[node];
    float2 acc = inp[(size_t)node * 32 + lane];
    acc.x *= d; acc.y *= d;                     // self-loop: xw[i]*dis[i]
    int s = g_off[node], e = g_off[node + 1];
    for (int base = s; base < e; base += 32) {
        int idx = base + lane;
        int2 pr = (idx < e) ? g_csr[idx] : make_int2(0, 0);
        int cnt = min(32, e - base);
        for (int j = 0; j < cnt; j++) {
            int row  = __shfl_sync(0xffffffffu, pr.x, j);
            float dw = __int_as_float(__shfl_sync(0xffffffffu, pr.y, j));
            float2 v = inp[(size_t)row * 32 + lane];
            acc.x = fmaf(v.x, dw, acc.x);
            acc.y = fmaf(v.y, dw, acc.y);
        }
    }
    float2 bv = ((const float2*)bias)[lane];
    float ox = fmaf(d, acc.x, bv.x);
    float oy = fmaf(d, acc.y, bv.y);
    if (relu) { ox = fmaxf(ox, 0.f); oy = fmaxf(oy, 0.f); }
    float2 o; o.x = ox; o.y = oy;
    ((float2*)out)[(size_t)node * 32 + lane] = o;
}

// ---------------- Decode: out[e] = dot(z[src], z[dst]) ----------------
__global__ void k_decode(const int* __restrict__ eli, const float* __restrict__ z,
                         float* __restrict__ out, int nL) {
    int w = blockIdx.x * 8 + (threadIdx.x >> 5);
    int lane = threadIdx.x & 31;
    if (w >= nL) return;
    int s = eli[w];
    int d = eli[nL + w];
    const float2* z2 = (const float2*)z;
    float2 a = z2[(size_t)s * 32 + lane];
    float2 b = z2[(size_t)d * 32 + lane];
    float p = a.x * b.x + a.y * b.y;
#pragma unroll
    for (int o = 16; o > 0; o >>= 1) p += __shfl_down_sync(0xffffffffu, p, o);
    if (lane == 0) out[w] = p;
}

// ---------------- launch ----------------
extern "C" void kernel_launch(void* const* d_in, const int* in_sizes, int n_in,
                              void* d_out, int out_size) {
    const float* x   = (const float*)d_in[0];
    const int*   ei  = (const int*)  d_in[1];
    const int*   eli = (const int*)  d_in[2];
    const float* W1  = (const float*)d_in[3];
    const float* b1  = (const float*)d_in[4];
    const float* W2  = (const float*)d_in[5];
    const float* b2  = (const float*)d_in[6];
    float* out = (float*)d_out;

    int n  = in_sizes[0] / 256;
    int nE = in_sizes[1] / 2;
    int nL = in_sizes[2] / 2;

    void *p_xw1, *p_h, *p_xw2, *p_z;
    cudaGetSymbolAddress(&p_xw1, g_xw1);
    cudaGetSymbolAddress(&p_h,   g_h);
    cudaGetSymbolAddress(&p_xw2, g_xw2);
    cudaGetSymbolAddress(&p_z,   g_z);

    // Fork: CSR build on side stream, GEMM1 concurrently on main stream.
    cudaEventRecord(g_evF, 0);
    cudaStreamWaitEvent(g_s2, g_evF, 0);

    k_count<<<(nE + 255) / 256, 256, 0, g_s2>>>(ei, nE);
    int nb = (n + 1023) / 1024;
    k_scan_fused<<<nb, 1024, 0, g_s2>>>(n, nb);
    k_scatter<<<(nE + 255) / 256, 256, 0, g_s2>>>(ei, nE);
    cudaEventRecord(g_evJ, g_s2);

    int gb = (n + 127) / 128;
    k_gemm_mma<256><<<gb, 256>>>(x, W1, (float*)p_xw1, n);   // concurrent with CSR

    // Join
    cudaStreamWaitEvent(0, g_evJ, 0);

    // layer 1 aggregate
    k_aggregate<<<(n + 7) / 8, 256>>>((const float*)p_xw1, (float*)p_h, b1, n, 1);
    // layer 2
    k_gemm_mma<64><<<gb, 256>>>((const float*)p_h, W2, (float*)p_xw2, n);
    k_aggregate<<<(n + 7) / 8, 256>>>((const float*)p_xw2, (float*)p_z, b2, n, 0);
    // decode
    k_decode<<<(nL + 7) / 8, 256>>>(eli, (const float*)p_z, out, nL);
}